// round 2
// baseline (speedup 1.0000x reference)
#include <cuda_runtime.h>
#include <cuda_bf16.h>
#include <cstdint>

// Problem constants (fixed by the dataset)
#define N_NODES 50000
#define D_IN    128
#define D_H     128
#define D_OUT   64
#define N_EDGES 800000
#define LN_EPS  1e-5f

// Scratch ping-pong buffers (allocation-free rule: __device__ globals)
__device__ float g_xw[N_NODES * D_H];  // holds h @ W for current layer
__device__ float g_h [N_NODES * D_H];  // holds post-LN hidden state

// ---------------------------------------------------------------------------
// GEMM: C[M, DOUT] = A[M,128] @ W[128, DOUT], fp32.
// Block: 256 threads, computes a 64-row tile over all DOUT columns.
// Whole W lives in smem (16/32K floats); A tile 64x128 in smem.
// Each thread: 8 rows x (DOUT/32) cols of accumulators.
// ---------------------------------------------------------------------------
template<int DOUT>
__global__ void __launch_bounds__(256)
gemm_kernel(const float* __restrict__ A, const float* __restrict__ W,
            float* __restrict__ C, int M)
{
    extern __shared__ float smem[];
    float* Ws = smem;                 // [128][DOUT]
    float* As = smem + 128 * DOUT;    // [64][128]

    const int tid = threadIdx.x;
    const int m0  = blockIdx.x * 64;

    // Load W (128*DOUT floats) vectorized
    for (int i = tid; i < 128 * DOUT / 4; i += 256)
        ((float4*)Ws)[i] = ((const float4*)W)[i];

    // Load A tile (64 rows x 128 cols), zero-fill past M
    for (int i = tid; i < 64 * 32; i += 256) {
        int r  = i >> 5;
        int c4 = i & 31;
        float4 v = make_float4(0.f, 0.f, 0.f, 0.f);
        if (m0 + r < M)
            v = ((const float4*)(A + (size_t)(m0 + r) * 128))[c4];
        ((float4*)As)[r * 32 + c4] = v;
    }
    __syncthreads();

    const int tx = tid & 31;    // column group (32 groups)
    const int ty = tid >> 5;    // row group (8 groups of 8 rows)
    constexpr int CPT = DOUT / 32;  // cols per thread: 4 (DOUT=128) or 2 (DOUT=64)

    float acc[8][CPT];
    #pragma unroll
    for (int r = 0; r < 8; ++r)
        #pragma unroll
        for (int c = 0; c < CPT; ++c) acc[r][c] = 0.f;

    #pragma unroll 4
    for (int k = 0; k < 128; ++k) {
        float a[8];
        #pragma unroll
        for (int r = 0; r < 8; ++r)
            a[r] = As[(ty * 8 + r) * 128 + k];   // warp-broadcast LDS

        float w[CPT];
        if (CPT == 4) {
            float4 w4 = ((const float4*)(Ws + k * DOUT))[tx];
            w[0] = w4.x; w[1] = w4.y; w[2] = w4.z; w[3] = w4.w;
        } else {
            float2 w2 = ((const float2*)(Ws + k * DOUT))[tx];
            w[0] = w2.x; w[1] = w2.y;
        }

        #pragma unroll
        for (int r = 0; r < 8; ++r)
            #pragma unroll
            for (int c = 0; c < CPT; ++c)
                acc[r][c] = fmaf(a[r], w[c], acc[r][c]);
    }

    // Store
    #pragma unroll
    for (int r = 0; r < 8; ++r) {
        int row = m0 + ty * 8 + r;
        if (row < M) {
            float* dst = C + (size_t)row * DOUT + tx * CPT;
            if (CPT == 4) {
                float4 v = make_float4(acc[r][0], acc[r][1], acc[r][2], acc[r][3]);
                *(float4*)dst = v;
            } else {
                float2 v = make_float2(acc[r][0], acc[r][1]);
                *(float2*)dst = v;
            }
        }
    }
}

// ---------------------------------------------------------------------------
// SpMM + LayerNorm (+ReLU): one warp per destination node.
// acc[lane*V + v] = sum over edges of xw[col][lane*V + v]; then LN across D.
// ---------------------------------------------------------------------------
template<int D, bool RELU>
__global__ void __launch_bounds__(256)
spmm_ln_kernel(const float* __restrict__ xw,
               const int* __restrict__ rowptr,
               const int* __restrict__ cols,
               float* __restrict__ out, int Nn)
{
    const int warp_in_block = threadIdx.x >> 5;
    const int node = blockIdx.x * (blockDim.x >> 5) + warp_in_block;
    if (node >= Nn) return;
    const int lane = threadIdx.x & 31;
    constexpr int V = D / 32;   // 4 (D=128) or 2 (D=64)

    float acc[V];
    #pragma unroll
    for (int v = 0; v < V; ++v) acc[v] = 0.f;

    const int s = __ldg(&rowptr[node]);
    const int e = __ldg(&rowptr[node + 1]);

    for (int i = s; i < e; ++i) {
        const int c = __ldg(&cols[i]);
        const float* row = xw + (size_t)c * D;
        if (V == 4) {
            float4 r4 = *(const float4*)(row + lane * 4);
            acc[0] += r4.x; acc[1] += r4.y; acc[2] += r4.z; acc[3] += r4.w;
        } else {
            float2 r2 = *(const float2*)(row + lane * 2);
            acc[0] += r2.x; acc[1] += r2.y;
        }
    }

    // LayerNorm over D values held across the warp
    float sum = 0.f, sumsq = 0.f;
    #pragma unroll
    for (int v = 0; v < V; ++v) { sum += acc[v]; sumsq += acc[v] * acc[v]; }
    #pragma unroll
    for (int off = 16; off > 0; off >>= 1) {
        sum   += __shfl_xor_sync(0xFFFFFFFFu, sum,   off);
        sumsq += __shfl_xor_sync(0xFFFFFFFFu, sumsq, off);
    }
    const float inv_d = 1.f / (float)D;
    const float mean = sum * inv_d;
    float var = sumsq * inv_d - mean * mean;
    if (var < 0.f) var = 0.f;           // numerical guard
    const float rstd = rsqrtf(var + LN_EPS);

    float y[V];
    #pragma unroll
    for (int v = 0; v < V; ++v) {
        float t = (acc[v] - mean) * rstd;
        if (RELU) t = fmaxf(t, 0.f);
        y[v] = t;
    }

    float* dst = out + (size_t)node * D + lane * V;
    if (V == 4) *(float4*)dst = make_float4(y[0], y[1], y[2], y[3]);
    else        *(float2*)dst = make_float2(y[0], y[1]);
}

// ---------------------------------------------------------------------------
// Launch
// ---------------------------------------------------------------------------
extern "C" void kernel_launch(void* const* d_in, const int* in_sizes, int n_in,
                              void* d_out, int out_size)
{
    // Identify inputs by element count (dict order: feat, W0, W1, W2,
    // nodePointer, edgeList, edge_rows). Duplicated sizes resolved in order.
    const float* feat = nullptr;
    const float* W0 = nullptr, *W1 = nullptr, *W2 = nullptr;
    const int* rowptr = nullptr;
    const int* elist  = nullptr;

    for (int i = 0; i < n_in; ++i) {
        const int sz = in_sizes[i];
        if (sz == N_NODES * D_IN)      feat = (const float*)d_in[i];
        else if (sz == D_IN * D_H) {
            if (!W0) W0 = (const float*)d_in[i];
            else     W1 = (const float*)d_in[i];
        }
        else if (sz == D_H * D_OUT)    W2 = (const float*)d_in[i];
        else if (sz == N_NODES + 1)    rowptr = (const int*)d_in[i];
        else if (sz == N_EDGES) {
            if (!elist) elist = (const int*)d_in[i];
            // second 800000-array is edge_rows: redundant with CSR rowptr
        }
    }

    float* xw = nullptr;
    float* h  = nullptr;
    cudaGetSymbolAddress((void**)&xw, g_xw);
    cudaGetSymbolAddress((void**)&h,  g_h);

    // Opt-in to >48KB dynamic smem for the GEMMs
    const int smem128 = (128 * 128 + 64 * 128) * (int)sizeof(float); // 96 KB
    const int smem64  = (128 * 64  + 64 * 128) * (int)sizeof(float); // 64 KB
    cudaFuncSetAttribute(gemm_kernel<128>,
                         cudaFuncAttributeMaxDynamicSharedMemorySize, smem128);
    cudaFuncSetAttribute(gemm_kernel<64>,
                         cudaFuncAttributeMaxDynamicSharedMemorySize, smem64);

    const int gemm_grid = (N_NODES + 63) / 64;
    const int spmm_grid = (N_NODES + 7) / 8;   // 8 warps (nodes) per block

    // Layer 0: feat @ W0 -> xw; SpMM+LN+ReLU -> h
    gemm_kernel<128><<<gemm_grid, 256, smem128>>>(feat, W0, xw, N_NODES);
    spmm_ln_kernel<128, true><<<spmm_grid, 256>>>(xw, rowptr, elist, h, N_NODES);

    // Layer 1: h @ W1 -> xw; SpMM+LN+ReLU -> h
    gemm_kernel<128><<<gemm_grid, 256, smem128>>>(h, W1, xw, N_NODES);
    spmm_ln_kernel<128, true><<<spmm_grid, 256>>>(xw, rowptr, elist, h, N_NODES);

    // Layer 2: h @ W2 -> xw; SpMM+LN (no ReLU) -> d_out
    gemm_kernel<64><<<gemm_grid, 256, smem64>>>(h, W2, xw, N_NODES);
    spmm_ln_kernel<64, false><<<spmm_grid, 256>>>(xw, rowptr, elist,
                                                  (float*)d_out, N_NODES);
}